// round 2
// baseline (speedup 1.0000x reference)
#include <cuda_runtime.h>
#include <cstdint>
#include <math.h>

#define B     4096
#define NIN   784
#define H1    100
#define H2    10
#define TSTEPS 100
#define TBEGIN 20

#define RPB   32            // rows per block
#define NBLK  (B / RPB)     // 128 CTAs
#define NTH   224           // 7 warps; 200 active in FMA phase (8x25 thread grid)
#define BK    16
#define NKT   (NIN / BK)    // 49

// ---- persistent state (device globals; no allocation allowed) ----
__device__ float g_inner1[B * H1];
__device__ float g_outer1[B * H1];
__device__ float g_inner2[B * H2];
__device__ float g_accum [B * H2];

// ---- JAX threefry2x32 (20 rounds), exact ----
__device__ __forceinline__ void tf2x32(uint32_t k0, uint32_t k1,
                                       uint32_t c0, uint32_t c1,
                                       uint32_t& o0, uint32_t& o1) {
    const uint32_t ks2 = k0 ^ k1 ^ 0x1BD11BDAu;
    uint32_t x0 = c0 + k0;
    uint32_t x1 = c1 + k1;
#define TF_RND(r) { x0 += x1; x1 = __funnelshift_l(x1, x1, (r)); x1 ^= x0; }
    TF_RND(13) TF_RND(15) TF_RND(26) TF_RND(6)
    x0 += k1;  x1 += ks2 + 1u;
    TF_RND(17) TF_RND(29) TF_RND(16) TF_RND(24)
    x0 += ks2; x1 += k0 + 2u;
    TF_RND(13) TF_RND(15) TF_RND(26) TF_RND(6)
    x0 += k0;  x1 += k1 + 3u;
    TF_RND(17) TF_RND(29) TF_RND(16) TF_RND(24)
    x0 += k1;  x1 += ks2 + 4u;
    TF_RND(13) TF_RND(15) TF_RND(26) TF_RND(6)
    x0 += ks2; x1 += k0 + 5u;
#undef TF_RND
    o0 = x0; o1 = x1;
}

// uniform [0,1): jax mapping, partitionable 32-bit fold = y0 ^ y1
__device__ __forceinline__ float tf_uniform(uint32_t key0, uint32_t key1, uint32_t idx) {
    uint32_t y0, y1;
    tf2x32(key0, key1, 0u, idx, y0, y1);
    uint32_t bits = y0 ^ y1;
    return __uint_as_float((bits >> 9) | 0x3f800000u) - 1.0f;
}

// One timestep, fully fused. Each CTA owns rows [r0, r0+32).
__global__ void __launch_bounds__(NTH)
step_kernel(const float* __restrict__ x,  const float* __restrict__ W1,
            const float* __restrict__ b1, const float* __restrict__ W2,
            const float* __restrict__ b2, int t)
{
    // 16-byte-aligned tiles FIRST (LDS.128 targets) — R1 failed on 8-mod-16
    // shared base addresses for these arrays.
    __shared__ __align__(16) float s_a[RPB][BK];        // xi tile, 2 KB (64 B rows)
    __shared__ __align__(16) float s_b[BK][H1 + 4];     // W1 tile, 416 B rows
    __shared__ float s_w2[H1 * H2];                     // 4000 B (scalar access only)
    __shared__ float s_b2[H2];

    const int tid = threadIdx.x;
    const int r0  = blockIdx.x * RPB;

    // step key: partitionable split -> threefry((0,42), (0,t))
    uint32_t key0, key1;
    tf2x32(0u, 42u, 0u, (uint32_t)t, key0, key1);

    for (int i = tid; i < H1 * H2; i += NTH) s_w2[i] = W2[i];
    if (tid < H2) s_b2[tid] = b2[tid];
    __syncthreads();

    // ---- layer 2: input is PREVIOUS-step layer1 spikes (delayed semantics);
    //      collected value is inner2 BEFORE this step's update ----
    for (int o = tid; o < RPB * H2; o += NTH) {
        const int lr = o / H2, n = o - lr * H2;
        const int row = r0 + lr;
        float acc = 0.f;
        if (t > 0) {
            const float* __restrict__ po1 = &g_outer1[row * H1];
            #pragma unroll 4
            for (int j = 0; j < H1; j++)
                acc = __fadd_rn(acc, __fmul_rn(po1[j], s_w2[j * H2 + n]));
        }
        const float exc   = __fadd_rn(acc, s_b2[n]);
        const int   gi    = row * H2 + n;
        const float i2old = (t == 0) ? 0.f : g_inner2[gi];
        if (t == 0)            g_accum[gi] = 0.f;
        else if (t >= TBEGIN)  g_accum[gi] = __fadd_rn(g_accum[gi], i2old);
        const float pre  = __fadd_rn(exc, __fmul_rn(i2old, 0.9f));
        const float gate = (pre > 1.0f) ? 1.0f : 0.0f;
        g_inner2[gi] = __fsub_rn(pre, __fmul_rn(gate, __fmul_rn(1.5f, pre)));
    }

    // ---- layer 1 GEMM: (u ⊙ x)[32,784] @ W1[784,100], RNG generated on the fly ----
    const int rg = tid / 25;          // 0..7  (rows rg*4 .. rg*4+3)
    const int cg = tid - rg * 25;     // 0..24 (cols cg*4 .. cg*4+3)
    const bool active = (tid < 200);

    float acc[4][4];
    #pragma unroll
    for (int i = 0; i < 4; i++)
        #pragma unroll
        for (int j = 0; j < 4; j++) acc[i][j] = 0.f;

    #pragma unroll 1
    for (int kt = 0; kt < NKT; kt++) {
        const int k0 = kt * BK;
        __syncthreads();
        // A tile with RNG: 32 x 16 (coalesced x reads; conflict-free smem writes)
        for (int i = tid; i < RPB * BK; i += NTH) {
            const int r = i >> 4, kk = i & 15;
            const uint32_t idx = (uint32_t)((r0 + r) * NIN + k0 + kk);
            const float u = tf_uniform(key0, key1, idx);
            s_a[r][kk] = __fmul_rn(u, x[idx]);
        }
        // W1 tile: 16 x 100
        for (int i = tid; i < BK * H1; i += NTH) {
            const int kk = i / H1, c = i - kk * H1;
            s_b[kk][c] = W1[(k0 + kk) * H1 + c];
        }
        __syncthreads();
        if (active) {
            #pragma unroll
            for (int kk = 0; kk < BK; kk += 4) {
                float4 a0 = *(const float4*)&s_a[rg * 4 + 0][kk];
                float4 a1 = *(const float4*)&s_a[rg * 4 + 1][kk];
                float4 a2 = *(const float4*)&s_a[rg * 4 + 2][kk];
                float4 a3 = *(const float4*)&s_a[rg * 4 + 3][kk];
                float4 b0 = *(const float4*)&s_b[kk + 0][cg * 4];
                float4 b1v = *(const float4*)&s_b[kk + 1][cg * 4];
                float4 b2v = *(const float4*)&s_b[kk + 2][cg * 4];
                float4 b3v = *(const float4*)&s_b[kk + 3][cg * 4];
                #define MAC(ai, i_) \
                    acc[i_][0] = fmaf(ai.x, b0.x,  acc[i_][0]); \
                    acc[i_][0] = fmaf(ai.y, b1v.x, acc[i_][0]); \
                    acc[i_][0] = fmaf(ai.z, b2v.x, acc[i_][0]); \
                    acc[i_][0] = fmaf(ai.w, b3v.x, acc[i_][0]); \
                    acc[i_][1] = fmaf(ai.x, b0.y,  acc[i_][1]); \
                    acc[i_][1] = fmaf(ai.y, b1v.y, acc[i_][1]); \
                    acc[i_][1] = fmaf(ai.z, b2v.y, acc[i_][1]); \
                    acc[i_][1] = fmaf(ai.w, b3v.y, acc[i_][1]); \
                    acc[i_][2] = fmaf(ai.x, b0.z,  acc[i_][2]); \
                    acc[i_][2] = fmaf(ai.y, b1v.z, acc[i_][2]); \
                    acc[i_][2] = fmaf(ai.z, b2v.z, acc[i_][2]); \
                    acc[i_][2] = fmaf(ai.w, b3v.z, acc[i_][2]); \
                    acc[i_][3] = fmaf(ai.x, b0.w,  acc[i_][3]); \
                    acc[i_][3] = fmaf(ai.y, b1v.w, acc[i_][3]); \
                    acc[i_][3] = fmaf(ai.z, b2v.w, acc[i_][3]); \
                    acc[i_][3] = fmaf(ai.w, b3v.w, acc[i_][3]);
                MAC(a0, 0) MAC(a1, 1) MAC(a2, 2) MAC(a3, 3)
                #undef MAC
            }
        }
    }

    // ---- layer 1 state update (rounding order replicates XLA elementwise ops) ----
    if (active) {
        #pragma unroll
        for (int i = 0; i < 4; i++) {
            const int row = r0 + rg * 4 + i;
            #pragma unroll
            for (int j = 0; j < 4; j++) {
                const int c  = cg * 4 + j;
                const int gi = row * H1 + c;
                const float exc  = __fadd_rn(acc[i][j], __ldg(&b1[c]));
                const float prev = (t == 0) ? 0.f : g_inner1[gi];
                const float pre  = __fadd_rn(exc, __fmul_rn(prev, 0.9f));
                const float outv = fmaxf(__fsub_rn(pre, 1.0f), 0.f);
                const float gate = (pre > 1.0f) ? 1.0f : 0.0f;
                g_inner1[gi] = __fsub_rn(pre, __fmul_rn(gate, __fmul_rn(1.5f, pre)));
                g_outer1[gi] = outv;
            }
        }
    }
}

__global__ void lsm_kernel(float* __restrict__ out) {
    const int row = blockIdx.x * blockDim.x + threadIdx.x;
    if (row >= B) return;
    float v[H2];
    float m = -INFINITY;
    #pragma unroll
    for (int n = 0; n < H2; n++) { v[n] = g_accum[row * H2 + n]; m = fmaxf(m, v[n]); }
    float s = 0.f;
    #pragma unroll
    for (int n = 0; n < H2; n++) s += expf(v[n] - m);
    const float ls = logf(s);
    #pragma unroll
    for (int n = 0; n < H2; n++) out[row * H2 + n] = v[n] - m - ls;
}

extern "C" void kernel_launch(void* const* d_in, const int* in_sizes, int n_in,
                              void* d_out, int out_size) {
    const float* x  = (const float*)d_in[0];
    const float* W1 = (const float*)d_in[1];
    const float* b1 = (const float*)d_in[2];
    const float* W2 = (const float*)d_in[3];
    const float* b2 = (const float*)d_in[4];
    for (int t = 0; t < TSTEPS; t++)
        step_kernel<<<NBLK, NTH>>>(x, W1, b1, W2, b2, t);
    lsm_kernel<<<(B + 255) / 256, 256>>>((float*)d_out);
}

// round 3
// speedup vs baseline: 2.2597x; 2.2597x over previous
#include <cuda_runtime.h>
#include <cstdint>
#include <math.h>

#define BSZ   4096
#define NIN   784
#define H1    100
#define H2    10
#define TSTEPS 100
#define TBEGIN 20

#define RPB   32            // rows per CTA
#define NBLK  (BSZ / RPB)   // 128 CTAs
#define NTH   640           // 20 warps: 0-6 consumers (200 active), 7-19 producers (416)
#define NPROD 416
#define BK    16
#define NKT   (NIN / BK)    // 49

// ---- JAX threefry2x32 (20 rounds), exact ----
__device__ __forceinline__ void tf2x32(uint32_t k0, uint32_t k1,
                                       uint32_t c0, uint32_t c1,
                                       uint32_t& o0, uint32_t& o1) {
    const uint32_t ks2 = k0 ^ k1 ^ 0x1BD11BDAu;
    uint32_t x0 = c0 + k0;
    uint32_t x1 = c1 + k1;
#define TF_RND(r) { x0 += x1; x1 = __funnelshift_l(x1, x1, (r)); x1 ^= x0; }
    TF_RND(13) TF_RND(15) TF_RND(26) TF_RND(6)
    x0 += k1;  x1 += ks2 + 1u;
    TF_RND(17) TF_RND(29) TF_RND(16) TF_RND(24)
    x0 += ks2; x1 += k0 + 2u;
    TF_RND(13) TF_RND(15) TF_RND(26) TF_RND(6)
    x0 += k0;  x1 += k1 + 3u;
    TF_RND(17) TF_RND(29) TF_RND(16) TF_RND(24)
    x0 += k1;  x1 += ks2 + 4u;
    TF_RND(13) TF_RND(15) TF_RND(26) TF_RND(6)
    x0 += ks2; x1 += k0 + 5u;
#undef TF_RND
    o0 = x0; o1 = x1;
}

__device__ __forceinline__ float tf_uniform(uint32_t key0, uint32_t key1, uint32_t idx) {
    uint32_t y0, y1;
    tf2x32(key0, key1, 0u, idx, y0, y1);
    uint32_t bits = y0 ^ y1;
    return __uint_as_float((bits >> 9) | 0x3f800000u) - 1.0f;
}

// packed fp32x2 helpers (each lane = exact IEEE fp32 -> bitwise same as scalar fmaf)
#define DUP64(d, f)  asm("mov.b64 %0, {%1, %1};" : "=l"(d) : "r"(__float_as_uint(f)))
#define FMA2(c, a, b) asm("fma.rn.f32x2 %0, %1, %2, %0;" : "+l"(c) : "l"(a), "l"(b))
#define UNPK(lo, hi, v) asm("mov.b64 {%0, %1}, %2;" : "=r"(lo), "=r"(hi) : "l"(v))

__global__ void __launch_bounds__(NTH, 1)
spiking_all(const float* __restrict__ x,  const float* __restrict__ W1,
            const float* __restrict__ b1, const float* __restrict__ W2,
            const float* __restrict__ b2, float* __restrict__ out)
{
    __shared__ __align__(16) float s_a[2][RPB][BK];      // 4 KB   (A = u.*x tiles)
    __shared__ __align__(16) float s_b[2][BK][H1 + 4];   // 13 KB  (W1 tiles)
    __shared__ float s_outer1[RPB][H1];                  // 12.8 KB (layer1 spikes)
    __shared__ float s_w2[H1 * H2];                      // 4 KB
    __shared__ float s_b1[H1];
    __shared__ float s_b2[H2];
    __shared__ float s_oacc[RPB * H2];                   // 1.28 KB (final accum)

    const int tid  = threadIdx.x;
    const int r0   = blockIdx.x * RPB;
    const int ptid = tid - 224;            // producer index, valid for tid>=224
    const int rg   = tid / 25;             // consumer: rows rg*4..rg*4+3 (tid<200)
    const int cg   = tid - rg * 25;        // consumer: cols cg*4..cg*4+3

    // ---- init params & state ----
    for (int i = tid; i < H1 * H2; i += NTH) s_w2[i] = W2[i];
    for (int i = tid; i < H1;      i += NTH) s_b1[i] = b1[i];
    if (tid < H2) s_b2[tid] = b2[tid];
    for (int i = tid; i < RPB * H1; i += NTH) ((float*)s_outer1)[i] = 0.f;

    // layer2 state: cell o = row*10+col. Thread tid<224 owns o=tid; tid<96 also o=224+tid.
    float i2a = 0.f, acca = 0.f, i2b = 0.f, accb = 0.f;
    // layer1 membrane state (consumer threads, 16 cells each)
    float inn[4][4] = {};
    unsigned long long acc2[4][2];

    __syncthreads();

    for (int t = 0; t < TSTEPS; t++) {
        // step key: threefry((0,42),(0,t))  (partitionable split)
        uint32_t key0, key1;
        tf2x32(0u, 42u, 0u, (uint32_t)t, key0, key1);

        // ---- phase A (overlapped): consumers do layer2 on PREVIOUS outer1,
        //      producers fill pipeline buffer 0 for kt=0 ----
        if (tid < 224) {
            #pragma unroll
            for (int half = 0; half < 2; half++) {
                if (half == 1 && tid >= 96) break;
                const int o   = half ? (224 + tid) : tid;
                const int lr  = o / H2, n = o - lr * H2;
                float& i2R  = half ? i2b  : i2a;
                float& accR = half ? accb : acca;
                float acc = 0.f;
                const float* __restrict__ po = &s_outer1[lr][0];
                #pragma unroll 4
                for (int j = 0; j < H1; j++)
                    acc = __fadd_rn(acc, __fmul_rn(po[j], s_w2[j * H2 + n]));
                const float exc = __fadd_rn(acc, s_b2[n]);
                if (t >= TBEGIN) accR = __fadd_rn(accR, i2R);
                const float pre  = __fadd_rn(exc, __fmul_rn(i2R, 0.9f));
                const float gate = (pre > 1.0f) ? 1.0f : 0.0f;
                i2R = __fsub_rn(pre, __fmul_rn(gate, __fmul_rn(1.5f, pre)));
            }
            // zero GEMM accumulators
            #pragma unroll
            for (int i = 0; i < 4; i++) { acc2[i][0] = 0ull; acc2[i][1] = 0ull; }
        } else {
            // produce tile 0 into buffer 0
            for (int i = ptid; i < RPB * BK; i += NPROD) {
                const int r = i >> 4, kk = i & 15;
                const uint32_t idx = (uint32_t)((r0 + r) * NIN + kk);
                const float u = tf_uniform(key0, key1, idx);
                s_a[0][r][kk] = __fmul_rn(u, x[idx]);
            }
            for (int i = ptid; i < 400; i += NPROD) {
                const int kk = i / 25, m = i - kk * 25;
                *(float4*)&s_b[0][kk][m * 4] = *(const float4*)&W1[kk * H1 + m * 4];
            }
        }
        __syncthreads();

        // ---- pipelined k-loop: consumers MAC buf[kt&1], producers fill buf[(kt+1)&1] ----
        for (int kt = 0; kt < NKT; kt++) {
            const int buf = kt & 1;
            if (tid < 200) {
                #pragma unroll
                for (int g = 0; g < BK; g += 4) {
                    float4 a0 = *(const float4*)&s_a[buf][rg * 4 + 0][g];
                    float4 a1 = *(const float4*)&s_a[buf][rg * 4 + 1][g];
                    float4 a2 = *(const float4*)&s_a[buf][rg * 4 + 2][g];
                    float4 a3 = *(const float4*)&s_a[buf][rg * 4 + 3][g];
                    ulonglong2 B0 = *(const ulonglong2*)&s_b[buf][g + 0][cg * 4];
                    ulonglong2 B1 = *(const ulonglong2*)&s_b[buf][g + 1][cg * 4];
                    ulonglong2 B2 = *(const ulonglong2*)&s_b[buf][g + 2][cg * 4];
                    ulonglong2 B3 = *(const ulonglong2*)&s_b[buf][g + 3][cg * 4];
                    #define MACROW(ai, i_) { \
                        unsigned long long dx, dy, dz, dw; \
                        DUP64(dx, ai.x); DUP64(dy, ai.y); DUP64(dz, ai.z); DUP64(dw, ai.w); \
                        FMA2(acc2[i_][0], dx, B0.x); FMA2(acc2[i_][0], dy, B1.x); \
                        FMA2(acc2[i_][0], dz, B2.x); FMA2(acc2[i_][0], dw, B3.x); \
                        FMA2(acc2[i_][1], dx, B0.y); FMA2(acc2[i_][1], dy, B1.y); \
                        FMA2(acc2[i_][1], dz, B2.y); FMA2(acc2[i_][1], dw, B3.y); }
                    MACROW(a0, 0) MACROW(a1, 1) MACROW(a2, 2) MACROW(a3, 3)
                    #undef MACROW
                }
            } else if (tid >= 224 && kt < NKT - 1) {
                const int k0 = (kt + 1) * BK;
                const int nbuf = buf ^ 1;
                for (int i = ptid; i < RPB * BK; i += NPROD) {
                    const int r = i >> 4, kk = i & 15;
                    const uint32_t idx = (uint32_t)((r0 + r) * NIN + k0 + kk);
                    const float u = tf_uniform(key0, key1, idx);
                    s_a[nbuf][r][kk] = __fmul_rn(u, x[idx]);
                }
                for (int i = ptid; i < 400; i += NPROD) {
                    const int kk = i / 25, m = i - kk * 25;
                    *(float4*)&s_b[nbuf][kk][m * 4] =
                        *(const float4*)&W1[(k0 + kk) * H1 + m * 4];
                }
            }
            __syncthreads();
        }

        // ---- layer1 state update (same rounding chain as before, bitwise) ----
        if (tid < 200) {
            #pragma unroll
            for (int i = 0; i < 4; i++) {
                const int lr = rg * 4 + i;
                #pragma unroll
                for (int p = 0; p < 2; p++) {
                    uint32_t ulo, uhi;
                    UNPK(ulo, uhi, acc2[i][p]);
                    #pragma unroll
                    for (int q = 0; q < 2; q++) {
                        const int   c    = cg * 4 + p * 2 + q;
                        const float accv = __uint_as_float(q ? uhi : ulo);
                        const float exc  = __fadd_rn(accv, s_b1[c]);
                        const float pre  = __fadd_rn(exc, __fmul_rn(inn[i][p * 2 + q], 0.9f));
                        const float outv = fmaxf(__fsub_rn(pre, 1.0f), 0.f);
                        const float gate = (pre > 1.0f) ? 1.0f : 0.0f;
                        inn[i][p * 2 + q] = __fsub_rn(pre, __fmul_rn(gate, __fmul_rn(1.5f, pre)));
                        s_outer1[lr][c] = outv;
                    }
                }
            }
        }
        __syncthreads();   // order state-update writes before next step's layer2 reads
    }

    // ---- epilogue: log_softmax per row ----
    if (tid < 224) s_oacc[tid] = acca;
    if (tid < 96)  s_oacc[224 + tid] = accb;
    __syncthreads();
    if (tid < RPB) {
        float v[H2];
        float m = -INFINITY;
        #pragma unroll
        for (int n = 0; n < H2; n++) { v[n] = s_oacc[tid * H2 + n]; m = fmaxf(m, v[n]); }
        float s = 0.f;
        #pragma unroll
        for (int n = 0; n < H2; n++) s += expf(v[n] - m);
        const float ls = logf(s);
        #pragma unroll
        for (int n = 0; n < H2; n++) out[(r0 + tid) * H2 + n] = v[n] - m - ls;
    }
}

extern "C" void kernel_launch(void* const* d_in, const int* in_sizes, int n_in,
                              void* d_out, int out_size) {
    const float* x  = (const float*)d_in[0];
    const float* W1 = (const float*)d_in[1];
    const float* b1 = (const float*)d_in[2];
    const float* W2 = (const float*)d_in[3];
    const float* b2 = (const float*)d_in[4];
    spiking_all<<<NBLK, NTH>>>(x, W1, b1, W2, b2, (float*)d_out);
}